// round 14
// baseline (speedup 1.0000x reference)
#include <cuda_runtime.h>

#define BB 16
#define NN 2048
#define EE 256

typedef unsigned long long ull;

// Scratch (__device__ globals; allocation-free rule)
__device__ float g_coef[5][EE];   // [0]=A0 [1]=A1 [2]=Dtop [3]=C [4]=Dbot+b_out
__device__ int   g_done;          // coef completion counter (monotonic across replays)

// ---- f32x2 helpers ---------------------------------------------------------
__device__ __forceinline__ ull fma2(ull a, ull b, ull c) {
    ull d;
    asm("fma.rn.f32x2 %0, %1, %2, %3;" : "=l"(d) : "l"(a), "l"(b), "l"(c));
    return d;
}
union F2U { ull u; float2 f; };
__device__ __forceinline__ ull pack2(float lo, float hi) {
    F2U t; t.f = make_float2(lo, hi); return t.u;
}
__device__ __forceinline__ void mina(float2& m, ull v) {
    F2U t; t.u = v;
    m.x = fminf(m.x, t.f.x);
    m.y = fminf(m.y, t.f.y);
}
__device__ __forceinline__ unsigned smem_u32(const void* p) {
    unsigned a;
    asm("{ .reg .u64 t; cvta.to.shared.u64 t, %1; cvt.u32.u64 %0, t; }"
        : "=r"(a) : "l"(p));
    return a;
}

// ---------------------------------------------------------------------------
// Single fused kernel: grid = 144 blocks, 256 threads, one wave.
//   blocks [0,128):   (batch, 256-row tile). Compaction, then a 4-stage
//                     pipeline of 64-row chunks: chunk-min (4 thr/row, one
//                     probe-quarter each) -> combine+sqrt -> stage -> TMA
//                     bulk store. Chunk c's drain overlaps chunk c+1's min.
//   blocks [128,136): top-half coefs (A0, A1, Dtop) -> g_done.
//   blocks [136,144): bottom-half coefs (C, Dbot+b_out) -> g_done.
// ---------------------------------------------------------------------------
__global__ __launch_bounds__(256) void fused_kernel(
    const float*    __restrict__ locs,
    const unsigned* __restrict__ probe_raw,
    const float*    __restrict__ W_node,
    const float*    __restrict__ b_node,
    const float*    __restrict__ W_dist,
    const float*    __restrict__ b_dist,
    const float*    __restrict__ W_out,
    const float*    __restrict__ b_out,
    float*          __restrict__ out)
{
    int blk = blockIdx.x;
    int tid = threadIdx.x;

    if (blk >= 128) {
        // ---- coefficient block (unchanged from R13) ----
        __shared__ float s_red[3][8][32];
        int top    = blk < 136;
        int t      = top ? (blk - 128) : (blk - 136);
        int elocal = tid & 31;
        int kg     = tid >> 5;
        int e      = t * 32 + elocal;
        int k0     = kg * 32;

        float a0 = 0.f, a1 = 0.f, dd = 0.f;
        if (top) {
            #pragma unroll 8
            for (int kk = 0; kk < 32; kk++) {
                int k = k0 + kk;
                float wt = W_out[k * EE + e];
                a0 = fmaf(W_node[k],      wt, a0);
                a1 = fmaf(W_node[EE + k], wt, a1);
                dd = fmaf(b_node[k],      wt, dd);
            }
        } else {
            #pragma unroll 8
            for (int kk = 0; kk < 32; kk++) {
                int k = k0 + kk;
                float wb = W_out[(EE + k) * EE + e];
                a0 = fmaf(W_dist[k], wb, a0);   // -> C
                dd = fmaf(b_dist[k], wb, dd);   // -> Dbot
            }
        }
        s_red[0][kg][elocal] = a0;
        s_red[1][kg][elocal] = a1;
        s_red[2][kg][elocal] = dd;
        __syncthreads();
        if (tid < 32) {
            float r0 = 0.f, r1 = 0.f, r2 = 0.f;
            #pragma unroll
            for (int g = 0; g < 8; g++) {
                r0 += s_red[0][g][tid];
                r1 += s_red[1][g][tid];
                r2 += s_red[2][g][tid];
            }
            int eo = t * 32 + tid;
            if (top) {
                g_coef[0][eo] = r0;
                g_coef[1][eo] = r1;
                g_coef[2][eo] = r2;
            } else {
                g_coef[3][eo] = r0;
                g_coef[4][eo] = r2 + b_out[eo];
            }
        }
        __syncthreads();
        __threadfence();
        if (tid == 0) atomicAdd(&g_done, 1);
        return;
    }

    // ---- pipeline block: (batch b, 256-row tile) ----
    extern __shared__ char dynbuf[];        // 2 x 64KB TMA staging
    __shared__ float4 s_xy4[NN / 2];        // pair-SoA (x0,x1,y0,y1), 16KB
    __shared__ ull    s_zz [NN / 2];        // pair (z0,z1), 8KB
    __shared__ int    s_wt[8];              // per-warp compaction totals
    __shared__ float  s_part[4][64];        // quarter partials for one chunk
    __shared__ float4 s_rowc[64];           // (x, y, md) for current chunk

    int b     = blk >> 3;
    int nbase = (blk & 7) << 8;
    int row0  = b * NN + nbase;

    // dtype detect on 512 words (valid reads under both candidate layouts)
    bool bad = false;
    #pragma unroll
    for (int j = 0; j < 2; j++) {
        unsigned v = probe_raw[b * 512 + j * 256 + tid];
        if (v != 0u && v != 1u && v != 0x3F800000u) bad = true;
    }
    int is8 = __syncthreads_or((int)bad);

    // wide loads: thread tid owns probes [tid*8, tid*8+8)
    unsigned hit[8];
    if (is8) {
        uint2 w = ((const uint2*)((const char*)probe_raw + (size_t)b * NN))[tid];
        hit[0] =  w.x        & 0xFFu;
        hit[1] = (w.x >>  8) & 0xFFu;
        hit[2] = (w.x >> 16) & 0xFFu;
        hit[3] = (w.x >> 24) & 0xFFu;
        hit[4] =  w.y        & 0xFFu;
        hit[5] = (w.y >>  8) & 0xFFu;
        hit[6] = (w.y >> 16) & 0xFFu;
        hit[7] = (w.y >> 24) & 0xFFu;
    } else {
        const uint4* p = (const uint4*)(probe_raw + (size_t)b * NN);
        uint4 w0 = p[tid * 2], w1 = p[tid * 2 + 1];
        hit[0] = w0.x; hit[1] = w0.y; hit[2] = w0.z; hit[3] = w0.w;
        hit[4] = w1.x; hit[5] = w1.y; hit[6] = w1.z; hit[7] = w1.w;
    }
    const float2* lp  = (const float2*)locs + b * NN;
    const float4* lp4 = (const float4*)lp;
    float4 l0 = lp4[tid * 4],     l1 = lp4[tid * 4 + 1];
    float4 l2 = lp4[tid * 4 + 2], l3 = lp4[tid * 4 + 3];
    float2 pl[8] = {
        {l0.x, l0.y}, {l0.z, l0.w}, {l1.x, l1.y}, {l1.z, l1.w},
        {l2.x, l2.y}, {l2.z, l2.w}, {l3.x, l3.y}, {l3.z, l3.w}
    };

    // deterministic compaction (identical across the 8 tile-blocks of a batch)
    int wid = tid >> 5, lid = tid & 31;
    unsigned lmask = (1u << lid) - 1u;
    unsigned bal[8];
    #pragma unroll
    for (int j = 0; j < 8; j++)
        bal[j] = __ballot_sync(0xFFFFFFFFu, hit[j] != 0u);
    if (lid == 0) {
        int t = 0;
        #pragma unroll
        for (int j = 0; j < 8; j++) t += __popc(bal[j]);
        s_wt[wid] = t;
    }
    __syncthreads();

    int base = 0, P = 0;
    #pragma unroll
    for (int w = 0; w < 8; w++) {
        int t = s_wt[w];
        if (w < wid) base += t;
        P += t;
    }

    float* sxyf = (float*)s_xy4;
    float* szf  = (float*)s_zz;
    {
        int run = base;
        #pragma unroll
        for (int j = 0; j < 8; j++) {
            if (hit[j] != 0u) {
                int q  = run + __popc(bal[j] & lmask);
                int pr = q >> 1, c = q & 1;
                sxyf[pr * 4 + c]     = pl[j].x;
                sxyf[pr * 4 + 2 + c] = pl[j].y;
                szf [pr * 2 + c]     = fmaf(pl[j].x, pl[j].x, pl[j].y * pl[j].y);
            }
            run += __popc(bal[j]);      // warp-uniform, register-only
        }
    }
    int Ppad = (P + 63) & ~63;          // probes, multiple of 64
    for (int q = P + tid; q < Ppad; q += 256) {
        int pr = q >> 1, c = q & 1;
        sxyf[pr * 4 + c]     = 0.f;
        sxyf[pr * 4 + 2 + c] = 0.f;
        szf [pr * 2 + c]     = 3.2e38f;
    }

    // ---- wait for coefficients (coef blocks run concurrently, ~same length
    //      as compaction; spin is usually near-zero) ----
    if (tid == 0) {
        while (atomicAdd(&g_done, 0) < 16) { }
    }
    __syncthreads();                    // also orders sentinel pads for min
    __threadfence();

    int e0 = (tid & 63) << 2;
    float4 A0 = *(const float4*)&g_coef[0][e0];
    float4 A1 = *(const float4*)&g_coef[1][e0];
    float4 Dt = *(const float4*)&g_coef[2][e0];
    float4 C  = *(const float4*)&g_coef[3][e0];
    float4 Db = *(const float4*)&g_coef[4][e0];
    float4 Dv = make_float4(Dt.x + Db.x, Dt.y + Db.y, Dt.z + Db.z, Dt.w + Db.w);

    // ---- chunked pipeline: min(c) -> stage(c) -> TMA(c), drain overlaps ----
    int q    = tid >> 6;                // probe quarter (warp-uniform)
    int r0   = tid & 63;                // row within chunk
    int rsub = tid >> 6;                // staging row-subgroup
    int npq  = Ppad >> 3;               // pairs per quarter (multiple of 4)
    int i0   = q * npq;
    const ulonglong2* sxy = (const ulonglong2*)s_xy4;

    #pragma unroll
    for (int c = 0; c < 4; c++) {
        if (c >= 2) {                   // gate buffer (c-2) reuse
            if (tid == 0)
                asm volatile("cp.async.bulk.wait_group 1;" ::: "memory");
            __syncthreads();
        }

        // min for this thread's row of chunk c over its probe quarter
        {
            float2 mm = lp[nbase + (c << 6) + r0];
            float ntx = -2.f * mm.x, nty = -2.f * mm.y;
            ull tx2 = pack2(ntx, ntx), ty2 = pack2(nty, nty);
            float2 m = make_float2(3.4e38f, 3.4e38f);
            int iend = i0 + npq;
            for (int i = i0; i < iend; i += 4) {
                ulonglong2 a0 = sxy[i],     a1 = sxy[i + 1];
                ulonglong2 a2 = sxy[i + 2], a3 = sxy[i + 3];
                ull z0 = s_zz[i],     z1 = s_zz[i + 1];
                ull z2 = s_zz[i + 2], z3 = s_zz[i + 3];
                mina(m, fma2(ty2, a0.y, fma2(tx2, a0.x, z0)));
                mina(m, fma2(ty2, a1.y, fma2(tx2, a1.x, z1)));
                mina(m, fma2(ty2, a2.y, fma2(tx2, a2.x, z2)));
                mina(m, fma2(ty2, a3.y, fma2(tx2, a3.x, z3)));
            }
            s_part[q][r0] = fminf(m.x, m.y);
        }
        __syncthreads();

        // combine quarters + sqrt for the chunk's 64 rows
        if (tid < 64) {
            float p0 = s_part[0][tid], p1 = s_part[1][tid];
            float p2 = s_part[2][tid], p3 = s_part[3][tid];
            float ms = fminf(fminf(p0, p1), fminf(p2, p3));
            float2 mm = lp[nbase + (c << 6) + tid];
            float d2 = fmaxf(fmaf(mm.x, mm.x, mm.y * mm.y) + ms, 0.f);
            s_rowc[tid] = make_float4(mm.x, mm.y, sqrtf(d2), 0.f);
        }
        __syncthreads();

        // stage 64 rows x 256 floats into buffer (c&1)
        float* buf = (float*)(dynbuf + (size_t)(c & 1) * 65536);
        #pragma unroll 16
        for (int rr = 0; rr < 64; rr += 4) {
            int lr = rr + rsub;
            float4 rw = s_rowc[lr];
            float4 v;
            v.x = fmaf(rw.x, A0.x, fmaf(rw.y, A1.x, fmaf(rw.z, C.x, Dv.x)));
            v.y = fmaf(rw.x, A0.y, fmaf(rw.y, A1.y, fmaf(rw.z, C.y, Dv.y)));
            v.z = fmaf(rw.x, A0.z, fmaf(rw.y, A1.z, fmaf(rw.z, C.z, Dv.z)));
            v.w = fmaf(rw.x, A0.w, fmaf(rw.y, A1.w, fmaf(rw.z, C.w, Dv.w)));
            *(float4*)(buf + (size_t)lr * EE + e0) = v;
        }
        __syncthreads();
        if (tid == 0) {
            asm volatile("fence.proxy.async;" ::: "memory");
            float*   gdst  = out + (size_t)(row0 + (c << 6)) * EE;
            unsigned saddr = smem_u32(buf);
            asm volatile(
                "cp.async.bulk.global.shared::cta.bulk_group [%0], [%1], %2;"
                :: "l"(gdst), "r"(saddr), "r"(65536u) : "memory");
            asm volatile("cp.async.bulk.commit_group;" ::: "memory");
        }
    }
    if (tid == 0)
        asm volatile("cp.async.bulk.wait_group 0;" ::: "memory");
}

// ---------------------------------------------------------------------------
extern "C" void kernel_launch(void* const* d_in, const int* in_sizes, int n_in,
                              void* d_out, int out_size)
{
    const float*    locs   = (const float*)d_in[0];
    const unsigned* probe  = (const unsigned*)d_in[1];
    const float*    W_node = (const float*)d_in[2];
    const float*    b_node = (const float*)d_in[3];
    const float*    W_dist = (const float*)d_in[4];
    const float*    b_dist = (const float*)d_in[5];
    const float*    W_out  = (const float*)d_in[6];
    const float*    b_out  = (const float*)d_in[7];
    float* out = (float*)d_out;

    cudaFuncSetAttribute(fused_kernel,
                         cudaFuncAttributeMaxDynamicSharedMemorySize, 131072);

    fused_kernel<<<144, 256, 131072>>>(locs, probe, W_node, b_node,
                                       W_dist, b_dist, W_out, b_out, out);
}

// round 15
// speedup vs baseline: 1.1472x; 1.1472x over previous
#include <cuda_runtime.h>

#define BB 16
#define NN 2048
#define EE 256

typedef unsigned long long ull;

// Scratch (__device__ globals; allocation-free rule)
__device__ float g_coef[5][EE];   // [0]=A0 [1]=A1 [2]=Dtop [3]=C [4]=Dbot+b_out
__device__ int   g_done;          // coef completion counter (monotonic across replays)

// ---- f32x2 helpers ---------------------------------------------------------
__device__ __forceinline__ ull fma2(ull a, ull b, ull c) {
    ull d;
    asm("fma.rn.f32x2 %0, %1, %2, %3;" : "=l"(d) : "l"(a), "l"(b), "l"(c));
    return d;
}
union F2U { ull u; float2 f; };
__device__ __forceinline__ ull pack2(float lo, float hi) {
    F2U t; t.f = make_float2(lo, hi); return t.u;
}
__device__ __forceinline__ void mina(float2& m, ull v) {
    F2U t; t.u = v;
    m.x = fminf(m.x, t.f.x);
    m.y = fminf(m.y, t.f.y);
}
__device__ __forceinline__ unsigned smem_u32(const void* p) {
    unsigned a;
    asm("{ .reg .u64 t; cvta.to.shared.u64 t, %1; cvt.u32.u64 %0, t; }"
        : "=r"(a) : "l"(p));
    return a;
}

// ---------------------------------------------------------------------------
// Single fused kernel: grid = 144 blocks, 256 threads, one wave.
//   blocks [0,128):   (batch, 256-row tile).
//     compaction -> chunk-0 md (G=1 fast path, 4 thr/row) -> coef spin ->
//     stage+store chunk 0 (TMA) -> full G=4 min pass (overlaps c0 drain) ->
//     stage+store chunks 1-3 (2-buffer TMA pipeline).
//   blocks [128,136): top-half coefs (A0, A1, Dtop) -> g_done.
//   blocks [136,144): bottom-half coefs (C, Dbot+b_out) -> g_done.
// ---------------------------------------------------------------------------
__global__ __launch_bounds__(256) void fused_kernel(
    const float*    __restrict__ locs,
    const unsigned* __restrict__ probe_raw,
    const float*    __restrict__ W_node,
    const float*    __restrict__ b_node,
    const float*    __restrict__ W_dist,
    const float*    __restrict__ b_dist,
    const float*    __restrict__ W_out,
    const float*    __restrict__ b_out,
    float*          __restrict__ out)
{
    int blk = blockIdx.x;
    int tid = threadIdx.x;

    if (blk >= 128) {
        // ---- coefficient block (unchanged) ----
        __shared__ float s_red[3][8][32];
        int top    = blk < 136;
        int t      = top ? (blk - 128) : (blk - 136);
        int elocal = tid & 31;
        int kg     = tid >> 5;
        int e      = t * 32 + elocal;
        int k0     = kg * 32;

        float a0 = 0.f, a1 = 0.f, dd = 0.f;
        if (top) {
            #pragma unroll 8
            for (int kk = 0; kk < 32; kk++) {
                int k = k0 + kk;
                float wt = W_out[k * EE + e];
                a0 = fmaf(W_node[k],      wt, a0);
                a1 = fmaf(W_node[EE + k], wt, a1);
                dd = fmaf(b_node[k],      wt, dd);
            }
        } else {
            #pragma unroll 8
            for (int kk = 0; kk < 32; kk++) {
                int k = k0 + kk;
                float wb = W_out[(EE + k) * EE + e];
                a0 = fmaf(W_dist[k], wb, a0);   // -> C
                dd = fmaf(b_dist[k], wb, dd);   // -> Dbot
            }
        }
        s_red[0][kg][elocal] = a0;
        s_red[1][kg][elocal] = a1;
        s_red[2][kg][elocal] = dd;
        __syncthreads();
        if (tid < 32) {
            float r0 = 0.f, r1 = 0.f, r2 = 0.f;
            #pragma unroll
            for (int g = 0; g < 8; g++) {
                r0 += s_red[0][g][tid];
                r1 += s_red[1][g][tid];
                r2 += s_red[2][g][tid];
            }
            int eo = t * 32 + tid;
            if (top) {
                g_coef[0][eo] = r0;
                g_coef[1][eo] = r1;
                g_coef[2][eo] = r2;
            } else {
                g_coef[3][eo] = r0;
                g_coef[4][eo] = r2 + b_out[eo];
            }
        }
        __syncthreads();
        __threadfence();
        if (tid == 0) atomicAdd(&g_done, 1);
        return;
    }

    // ---- pipeline block: (batch b, 256-row tile) ----
    extern __shared__ char dynbuf[];        // 2 x 64KB TMA staging
    __shared__ float4 s_xy4[NN / 2];        // pair-SoA (x0,x1,y0,y1), 16KB
    __shared__ ull    s_zz [NN / 2];        // pair (z0,z1), 8KB
    __shared__ int    s_wt[8];              // per-warp compaction totals
    __shared__ float  s_p0[4][64];          // chunk-0 quarter partials
    __shared__ float4 s_rowc[64];           // chunk-0 (x,y,md)
    __shared__ float  s_part[4][4][64];     // G=4 pass quarter partials
    __shared__ float4 s_row[256];           // full-tile (x,y,md)

    int b     = blk >> 3;
    int nbase = (blk & 7) << 8;
    int row0  = b * NN + nbase;

    // dtype detect on 512 words (valid reads under both candidate layouts)
    bool bad = false;
    #pragma unroll
    for (int j = 0; j < 2; j++) {
        unsigned v = probe_raw[b * 512 + j * 256 + tid];
        if (v != 0u && v != 1u && v != 0x3F800000u) bad = true;
    }
    int is8 = __syncthreads_or((int)bad);

    // wide loads: thread tid owns probes [tid*8, tid*8+8)
    unsigned hit[8];
    if (is8) {
        uint2 w = ((const uint2*)((const char*)probe_raw + (size_t)b * NN))[tid];
        hit[0] =  w.x        & 0xFFu;
        hit[1] = (w.x >>  8) & 0xFFu;
        hit[2] = (w.x >> 16) & 0xFFu;
        hit[3] = (w.x >> 24) & 0xFFu;
        hit[4] =  w.y        & 0xFFu;
        hit[5] = (w.y >>  8) & 0xFFu;
        hit[6] = (w.y >> 16) & 0xFFu;
        hit[7] = (w.y >> 24) & 0xFFu;
    } else {
        const uint4* p = (const uint4*)(probe_raw + (size_t)b * NN);
        uint4 w0 = p[tid * 2], w1 = p[tid * 2 + 1];
        hit[0] = w0.x; hit[1] = w0.y; hit[2] = w0.z; hit[3] = w0.w;
        hit[4] = w1.x; hit[5] = w1.y; hit[6] = w1.z; hit[7] = w1.w;
    }
    const float2* lp  = (const float2*)locs + b * NN;
    const float4* lp4 = (const float4*)lp;
    float4 l0 = lp4[tid * 4],     l1 = lp4[tid * 4 + 1];
    float4 l2 = lp4[tid * 4 + 2], l3 = lp4[tid * 4 + 3];
    float2 pl[8] = {
        {l0.x, l0.y}, {l0.z, l0.w}, {l1.x, l1.y}, {l1.z, l1.w},
        {l2.x, l2.y}, {l2.z, l2.w}, {l3.x, l3.y}, {l3.z, l3.w}
    };

    // deterministic compaction (identical across the 8 tile-blocks of a batch)
    int wid = tid >> 5, lid = tid & 31;
    unsigned lmask = (1u << lid) - 1u;
    unsigned bal[8];
    #pragma unroll
    for (int j = 0; j < 8; j++)
        bal[j] = __ballot_sync(0xFFFFFFFFu, hit[j] != 0u);
    if (lid == 0) {
        int t = 0;
        #pragma unroll
        for (int j = 0; j < 8; j++) t += __popc(bal[j]);
        s_wt[wid] = t;
    }
    __syncthreads();

    int base = 0, P = 0;
    #pragma unroll
    for (int w = 0; w < 8; w++) {
        int t = s_wt[w];
        if (w < wid) base += t;
        P += t;
    }

    float* sxyf = (float*)s_xy4;
    float* szf  = (float*)s_zz;
    {
        int run = base;
        #pragma unroll
        for (int j = 0; j < 8; j++) {
            if (hit[j] != 0u) {
                int q  = run + __popc(bal[j] & lmask);
                int pr = q >> 1, c = q & 1;
                sxyf[pr * 4 + c]     = pl[j].x;
                sxyf[pr * 4 + 2 + c] = pl[j].y;
                szf [pr * 2 + c]     = fmaf(pl[j].x, pl[j].x, pl[j].y * pl[j].y);
            }
            run += __popc(bal[j]);      // warp-uniform, register-only
        }
    }
    int Ppad = (P + 63) & ~63;          // probes, multiple of 64
    for (int q = P + tid; q < Ppad; q += 256) {
        int pr = q >> 1, c = q & 1;
        sxyf[pr * 4 + c]     = 0.f;
        sxyf[pr * 4 + 2 + c] = 0.f;
        szf [pr * 2 + c]     = 3.2e38f;
    }
    __syncthreads();

    int npq = Ppad >> 3;                // pairs per quarter (multiple of 4)
    const ulonglong2* sxy = (const ulonglong2*)s_xy4;

    // ---- chunk-0 fast md: 4 threads/row, one probe quarter each (G=1) ----
    {
        int q  = tid >> 6;              // warp-uniform quarter
        int r0 = tid & 63;
        float2 mm = lp[nbase + r0];
        float ntx = -2.f * mm.x, nty = -2.f * mm.y;
        ull tx2 = pack2(ntx, ntx), ty2 = pack2(nty, nty);
        float2 m = make_float2(3.4e38f, 3.4e38f);
        int i0 = q * npq, iend = i0 + npq;
        for (int i = i0; i < iend; i += 4) {
            ulonglong2 a0 = sxy[i],     a1 = sxy[i + 1];
            ulonglong2 a2 = sxy[i + 2], a3 = sxy[i + 3];
            ull z0 = s_zz[i],     z1 = s_zz[i + 1];
            ull z2 = s_zz[i + 2], z3 = s_zz[i + 3];
            mina(m, fma2(ty2, a0.y, fma2(tx2, a0.x, z0)));
            mina(m, fma2(ty2, a1.y, fma2(tx2, a1.x, z1)));
            mina(m, fma2(ty2, a2.y, fma2(tx2, a2.x, z2)));
            mina(m, fma2(ty2, a3.y, fma2(tx2, a3.x, z3)));
        }
        s_p0[q][r0] = fminf(m.x, m.y);
    }
    __syncthreads();
    if (tid < 64) {
        float p0 = s_p0[0][tid], p1 = s_p0[1][tid];
        float p2 = s_p0[2][tid], p3 = s_p0[3][tid];
        float ms = fminf(fminf(p0, p1), fminf(p2, p3));
        float2 mm = lp[nbase + tid];
        float d2 = fmaxf(fmaf(mm.x, mm.x, mm.y * mm.y) + ms, 0.f);
        s_rowc[tid] = make_float4(mm.x, mm.y, sqrtf(d2), 0.f);
    }

    // ---- coefficient spin (overlapped with the min work above) ----
    if (tid == 0) {
        while (atomicAdd(&g_done, 0) < 16) { }
    }
    __syncthreads();
    __threadfence();

    int e0 = (tid & 63) << 2;
    float4 A0 = *(const float4*)&g_coef[0][e0];
    float4 A1 = *(const float4*)&g_coef[1][e0];
    float4 Dt = *(const float4*)&g_coef[2][e0];
    float4 C  = *(const float4*)&g_coef[3][e0];
    float4 Db = *(const float4*)&g_coef[4][e0];
    float4 Dv = make_float4(Dt.x + Db.x, Dt.y + Db.y, Dt.z + Db.z, Dt.w + Db.w);
    int rsub = tid >> 6;

    // ---- stage + store chunk 0 immediately ----
    {
        float* buf = (float*)dynbuf;            // buffer 0
        #pragma unroll 16
        for (int rr = 0; rr < 64; rr += 4) {
            int lr = rr + rsub;
            float4 rw = s_rowc[lr];
            float4 v;
            v.x = fmaf(rw.x, A0.x, fmaf(rw.y, A1.x, fmaf(rw.z, C.x, Dv.x)));
            v.y = fmaf(rw.x, A0.y, fmaf(rw.y, A1.y, fmaf(rw.z, C.y, Dv.y)));
            v.z = fmaf(rw.x, A0.z, fmaf(rw.y, A1.z, fmaf(rw.z, C.z, Dv.z)));
            v.w = fmaf(rw.x, A0.w, fmaf(rw.y, A1.w, fmaf(rw.z, C.w, Dv.w)));
            *(float4*)(buf + (size_t)lr * EE + e0) = v;
        }
        __syncthreads();
        if (tid == 0) {
            asm volatile("fence.proxy.async;" ::: "memory");
            float*   gdst  = out + (size_t)row0 * EE;
            unsigned saddr = smem_u32(buf);
            asm volatile(
                "cp.async.bulk.global.shared::cta.bulk_group [%0], [%1], %2;"
                :: "l"(gdst), "r"(saddr), "r"(65536u) : "memory");
            asm volatile("cp.async.bulk.commit_group;" ::: "memory");
        }
    }

    // ---- full G=4 min pass (overlaps chunk-0 drain) ----
    {
        int q  = tid >> 6;              // warp-uniform quarter
        int r0 = tid & 63;
        float2 me[4];
        ull tx2[4], ty2[4];
        float2 m[4];
        #pragma unroll
        for (int g = 0; g < 4; g++) {
            me[g] = lp[nbase + r0 + (g << 6)];
            float ntx = -2.f * me[g].x, nty = -2.f * me[g].y;
            tx2[g] = pack2(ntx, ntx);
            ty2[g] = pack2(nty, nty);
            m[g]   = make_float2(3.4e38f, 3.4e38f);
        }
        int i0 = q * npq, iend = i0 + npq;
        for (int i = i0; i < iend; i += 4) {
            ulonglong2 a0 = sxy[i],     a1 = sxy[i + 1];
            ulonglong2 a2 = sxy[i + 2], a3 = sxy[i + 3];
            ull z0 = s_zz[i],     z1 = s_zz[i + 1];
            ull z2 = s_zz[i + 2], z3 = s_zz[i + 3];
            #pragma unroll
            for (int g = 0; g < 4; g++) {
                mina(m[g], fma2(ty2[g], a0.y, fma2(tx2[g], a0.x, z0)));
                mina(m[g], fma2(ty2[g], a1.y, fma2(tx2[g], a1.x, z1)));
                mina(m[g], fma2(ty2[g], a2.y, fma2(tx2[g], a2.x, z2)));
                mina(m[g], fma2(ty2[g], a3.y, fma2(tx2[g], a3.x, z3)));
            }
        }
        #pragma unroll
        for (int g = 0; g < 4; g++)
            s_part[q][g][r0] = fminf(m[g].x, m[g].y);
    }
    __syncthreads();
    {
        int gi = tid >> 6, ri = tid & 63;
        float p0 = s_part[0][gi][ri], p1 = s_part[1][gi][ri];
        float p2 = s_part[2][gi][ri], p3 = s_part[3][gi][ri];
        float ms = fminf(fminf(p0, p1), fminf(p2, p3));
        float2 mm = lp[nbase + tid];
        float d2 = fmaxf(fmaf(mm.x, mm.x, mm.y * mm.y) + ms, 0.f);
        s_row[tid] = make_float4(mm.x, mm.y, sqrtf(d2), 0.f);
    }
    __syncthreads();

    // ---- stage + store chunks 1..3 (2-buffer pipeline) ----
    #pragma unroll
    for (int c = 1; c < 4; c++) {
        if (c >= 2) {                   // gate buffer (c&1 ^ used) reuse
            if (tid == 0)
                asm volatile("cp.async.bulk.wait_group 1;" ::: "memory");
            __syncthreads();
        }
        float* buf   = (float*)(dynbuf + (size_t)(c & 1) * 65536);
        int    rbase = c << 6;
        #pragma unroll 16
        for (int rr = 0; rr < 64; rr += 4) {
            int lr = rr + rsub;
            float4 rw = s_row[rbase + lr];
            float4 v;
            v.x = fmaf(rw.x, A0.x, fmaf(rw.y, A1.x, fmaf(rw.z, C.x, Dv.x)));
            v.y = fmaf(rw.x, A0.y, fmaf(rw.y, A1.y, fmaf(rw.z, C.y, Dv.y)));
            v.z = fmaf(rw.x, A0.z, fmaf(rw.y, A1.z, fmaf(rw.z, C.z, Dv.z)));
            v.w = fmaf(rw.x, A0.w, fmaf(rw.y, A1.w, fmaf(rw.z, C.w, Dv.w)));
            *(float4*)(buf + (size_t)lr * EE + e0) = v;
        }
        __syncthreads();
        if (tid == 0) {
            asm volatile("fence.proxy.async;" ::: "memory");
            float*   gdst  = out + (size_t)(row0 + rbase) * EE;
            unsigned saddr = smem_u32(buf);
            asm volatile(
                "cp.async.bulk.global.shared::cta.bulk_group [%0], [%1], %2;"
                :: "l"(gdst), "r"(saddr), "r"(65536u) : "memory");
            asm volatile("cp.async.bulk.commit_group;" ::: "memory");
        }
    }
    if (tid == 0)
        asm volatile("cp.async.bulk.wait_group 0;" ::: "memory");
}

// ---------------------------------------------------------------------------
extern "C" void kernel_launch(void* const* d_in, const int* in_sizes, int n_in,
                              void* d_out, int out_size)
{
    const float*    locs   = (const float*)d_in[0];
    const unsigned* probe  = (const unsigned*)d_in[1];
    const float*    W_node = (const float*)d_in[2];
    const float*    b_node = (const float*)d_in[3];
    const float*    W_dist = (const float*)d_in[4];
    const float*    b_dist = (const float*)d_in[5];
    const float*    W_out  = (const float*)d_in[6];
    const float*    b_out  = (const float*)d_in[7];
    float* out = (float*)d_out;

    cudaFuncSetAttribute(fused_kernel,
                         cudaFuncAttributeMaxDynamicSharedMemorySize, 131072);

    fused_kernel<<<144, 256, 131072>>>(locs, probe, W_node, b_node,
                                       W_dist, b_dist, W_out, b_out, out);
}